// round 15
// baseline (speedup 1.0000x reference)
#include <cuda_runtime.h>
#include <cuda_fp16.h>

#define RR 256
#define CC 32

// Two fp16 copies of the triplane in [p][y][x][c]; copy B shifted by one
// 64B x-line (B[k] = A[k+32]) so every x-pair load is one aligned 128B line
// (select copy by x0&1). Zero-init tail pad covers the unclamped row-(y0+1)
// reads at y0=255 (their weight is exactly 0).
#define OFFH (3 * RR * RR * CC + 64)
#define OFF4 (OFFH / 8)
__device__ __align__(128) __half g_tph[2 * OFFH + 2048 * 8];

// Transpose+convert [p][c][y][x] fp32 -> [p][y][x][c] fp16, both copies.
// One block per (p, y): float4-coalesced reads, smem stage (stride 34 halves
// = 68B: 4B-aligned rows), 16B-coalesced stores (4/thread/copy). 768 blocks.
__global__ void __launch_bounds__(256) tp_transpose_kernel(const float* __restrict__ in) {
    __shared__ __half sm[256 * 34 + 8];   // [x][c], stride 34 halves
    int p = blockIdx.y;
    int y = blockIdx.x;

    // reads: 2048 float4 per block, 8 iterations, fully coalesced
    const float4* in4 = reinterpret_cast<const float4*>(in);
    #pragma unroll
    for (int i = threadIdx.x; i < 32 * 64; i += 256) {
        int c = i >> 6, x4 = i & 63;
        float4 v = __ldg(in4 + (((size_t)(p * CC + c) * RR + y) << 6) + x4);
        int x = x4 << 2;
        sm[(x + 0) * 34 + c] = __float2half(v.x);
        sm[(x + 1) * 34 + c] = __float2half(v.y);
        sm[(x + 2) * 34 + c] = __float2half(v.z);
        sm[(x + 3) * 34 + c] = __float2half(v.w);
    }
    __syncthreads();

    // writes: 1024 uint4 per (p,y) per copy, 4 per thread, fully coalesced
    uint4* g = reinterpret_cast<uint4*>(g_tph);
    size_t base4 = (size_t)((p * RR + y) * RR) * 4;    // uint4 index of x=0
    #pragma unroll
    for (int k = threadIdx.x; k < 1024; k += 256) {
        int x = k >> 2, q = k & 3;
        const unsigned* s = reinterpret_cast<const unsigned*>(sm + x * 34 + q * 8);
        uint4 v = make_uint4(s[0], s[1], s[2], s[3]);
        size_t pos4 = base4 + k;
        g[pos4] = v;
        if (pos4 >= 4) g[OFF4 + pos4 - 4] = v;         // B[k] = A[k+32 halves]
    }
}

__device__ __forceinline__ __half2 u2h2(unsigned u) {
    return *reinterpret_cast<__half2*>(&u);
}
__device__ __forceinline__ unsigned h22u(__half2 h) {
    return *reinterpret_cast<unsigned*>(&h);
}

// streaming (evict-first) 16B store: keep the 256MB output out of L2's way
__device__ __forceinline__ void stg_cs(float4* p, float4 v) {
    asm volatile("st.global.cs.v4.f32 [%0], {%1, %2, %3, %4};"
                 :: "l"(p), "f"(v.x), "f"(v.y), "f"(v.z), "f"(v.w) : "memory");
}

// Warp owns 32 consecutive points. Phase 1: coalesced xyz + SHFL
// redistribution, per-lane axis prep. Phase 2: partial depth-1 pipeline —
// planes 0,1 of iteration it+1 staged ahead (16 buffer regs); plane 2's two
// loads issued at the top of their own iteration. (Best measured config:
// regs 72, occ ~40%, sampler at its L1tex wavefront floor.)
__global__ void __launch_bounds__(128, 7) triplane_sample_kernel(
    const float* __restrict__ xyz, float* __restrict__ out, int M) {
    int lane = threadIdx.x & 31;
    int wgl  = (int)((blockIdx.x * (unsigned)blockDim.x + threadIdx.x) >> 5);
    int m0   = wgl * 32;
    if (m0 >= M) return;

    // ---- phase 1: coalesced xyz + shfl redistribution ----
    const float* xb = xyz + (size_t)m0 * 3;
    float r0 = __ldg(xb + lane);
    float r1 = __ldg(xb + 32 + lane);
    float r2 = __ldg(xb + 64 + lane);

    unsigned idx_pack = 0;
    unsigned wpack[3];
    #pragma unroll
    for (int d = 0; d < 3; d++) {
        int f     = 3 * lane + d;
        int chunk = f >> 5, src = f & 31;
        float v0 = __shfl_sync(0xffffffffu, r0, src);
        float v1 = __shfl_sync(0xffffffffu, r1, src);
        float v2 = __shfl_sync(0xffffffffu, r2, src);
        float cv = (chunk == 0) ? v0 : ((chunk == 1) ? v1 : v2);

        float i  = fminf(fmaxf(fmaf(cv, 127.5f, 127.5f), 0.0f), 255.0f);
        int   i0 = (int)i;                 // trunc == floor (i >= 0)
        float f1 = i - (float)i0;          // ==0 exactly at clamped edge
        idx_pack |= ((unsigned)i0) << (8 * d);
        wpack[d]  = h22u(__floats2half2_rn(1.0f - f1, f1));
    }

    int sub   = lane & 7;       // uint4 slot in the 128B x-pair region
    int grp   = lane >> 3;
    int xsel  = sub >> 2;       // 0: x0 tap, 1: x0+1 tap
    int shift = xsel << 4;
    const uint4* tp = reinterpret_cast<const uint4*>(g_tph);

    // stage iteration 'it': metadata SHFLs, all three base addresses,
    // and issue the plane-0/1 loads (plane 2 is issued at consume time)
    auto stage = [&](int it, unsigned& swx, unsigned& swy, unsigned& swz,
                     int& sb2, uint4* t) {
        int src = (it << 2) | grp;
        unsigned idx = __shfl_sync(0xffffffffu, idx_pack, src);
        swx = __shfl_sync(0xffffffffu, wpack[0], src);
        swy = __shfl_sync(0xffffffffu, wpack[1], src);
        swz = __shfl_sync(0xffffffffu, wpack[2], src);

        int ix = idx & 255;
        int iy = (idx >> 8) & 255;
        int iz = (idx >> 16) & 255;
        int cy = ((iy & 1) ? OFF4 : 0) + ((iy & 0xFE) << 2) + sub;
        int cz = ((iz & 1) ? OFF4 : 0) + ((iz & 0xFE) << 2) + sub;
        int b0 = cy + 0 * (RR * RR * 4) + (ix << 10);
        int b1 = cz + 1 * (RR * RR * 4) + (ix << 10);
        sb2    = cy + 2 * (RR * RR * 4) + (iz << 10);

        t[0] = __ldg(tp + b0);
        t[1] = __ldg(tp + b0 + 1024);   // row ix+1 (pad-safe)
        t[2] = __ldg(tp + b1);
        t[3] = __ldg(tp + b1 + 1024);
    };

    // ---- phase 2: 8 iterations x 4 points ----
    unsigned cwx, cwy, cwz;
    int cb2;
    uint4 cur[4];
    stage(0, cwx, cwy, cwz, cb2, cur);

    #pragma unroll
    for (int it = 0; it < 8; it++) {
        // plane 2 loads for the CURRENT iteration — issued first, consumed last
        uint4 t20u = __ldg(tp + cb2);
        uint4 t21u = __ldg(tp + cb2 + 1024);

        // stage next iteration (planes 0,1 + metadata) while t2* are in flight
        unsigned nwx, nwy, nwz;
        int nb2;
        uint4 nxt[4];
        if (it < 7) stage(it + 1, nwx, nwy, nwz, nb2, nxt);

        // weight splats
        auto mkw = [&](unsigned cwt, unsigned rwt, __half2& w0, __half2& w1) {
            __half2 wxh = u2h2(__byte_perm(cwt >> shift, 0, 0x1010));
            unsigned whu = h22u(__hmul2(u2h2(rwt), wxh));
            w0 = u2h2(__byte_perm(whu, 0, 0x1010));
            w1 = u2h2(__byte_perm(whu, 0, 0x3232));
        };
        __half2 w00, w01, w10, w11, w20, w21;
        mkw(cwy, cwx, w00, w01);   // plane0: col=y row=x
        mkw(cwz, cwx, w10, w11);   // plane1: col=z row=x
        mkw(cwy, cwz, w20, w21);   // plane2: col=y row=z

        const __half2* v00 = reinterpret_cast<const __half2*>(&cur[0]);
        const __half2* v01 = reinterpret_cast<const __half2*>(&cur[1]);
        const __half2* v10 = reinterpret_cast<const __half2*>(&cur[2]);
        const __half2* v11 = reinterpret_cast<const __half2*>(&cur[3]);
        const __half2* v20 = reinterpret_cast<const __half2*>(&t20u);
        const __half2* v21 = reinterpret_cast<const __half2*>(&t21u);

        __half2 acc[4];
        // planes 0,1 first (staged an iteration ago), plane 2 last
        #pragma unroll
        for (int j = 0; j < 4; j++) {
            __half2 a = __hmul2(v00[j], w00);
            a = __hfma2(v01[j], w01, a);
            a = __hfma2(v10[j], w10, a);
            acc[j] = __hfma2(v11[j], w11, a);
        }
        #pragma unroll
        for (int j = 0; j < 4; j++) {
            acc[j] = __hfma2(v20[j], w20, acc[j]);
            acc[j] = __hfma2(v21[j], w21, acc[j]);
        }

        // butterfly-sum the two x halves (partner = lane ^ 4)
        #pragma unroll
        for (int j = 0; j < 4; j++) {
            unsigned u = __shfl_xor_sync(0xffffffffu, h22u(acc[j]), 4);
            acc[j] = __hadd2(acc[j], u2h2(u));
        }

        int m  = m0 + (it << 2) + grp;
        int jb = xsel * 2;
        float2 f0 = __half22float2(acc[jb]);
        float2 f1 = __half22float2(acc[jb + 1]);
        stg_cs(reinterpret_cast<float4*>(out) + (size_t)m * 8 + (sub & 3) * 2 + xsel,
               make_float4(f0.x, f0.y, f1.x, f1.y));

        if (it < 7) {
            #pragma unroll
            for (int k = 0; k < 4; k++) cur[k] = nxt[k];
            cwx = nwx; cwy = nwy; cwz = nwz; cb2 = nb2;
        }
    }
}

extern "C" void kernel_launch(void* const* d_in, const int* in_sizes, int n_in,
                              void* d_out, int out_size) {
    const float* xyz      = (const float*)d_in[0];  // (M,3) float32
    const float* triplane = (const float*)d_in[1];  // (3,32,256,256) float32
    float* out = (float*)d_out;                      // (M,32) float32
    int M = in_sizes[0] / 3;

    {
        dim3 block(256, 1, 1);
        dim3 grid(RR, 3, 1);                // one block per (y, p)
        tp_transpose_kernel<<<grid, block>>>(triplane);
    }
    {
        int threads = 128;                  // 4 warps = 128 points per block
        int warps   = (M + 31) / 32;
        int blocks  = (warps * 32 + threads - 1) / threads;
        triplane_sample_kernel<<<blocks, threads>>>(xyz, out, M);
    }
}

// round 16
// speedup vs baseline: 1.0421x; 1.0421x over previous
#include <cuda_runtime.h>
#include <cuda_fp16.h>

#define RR 256
#define CC 32

// Two fp16 copies of the triplane in [p][y][x][c]; copy B shifted by one
// 64B x-line (B[k] = A[k+32]) so every x-pair load is one aligned 128B line
// (select copy by x0&1). Zero-init tail pad covers the unclamped row-(y0+1)
// reads at y0=255 (their weight is exactly 0).
#define OFFH (3 * RR * RR * CC + 64)
#define OFF4 (OFFH / 8)
__device__ __align__(128) __half g_tph[2 * OFFH + 2048 * 8];

// Transpose+convert [p][c][y][x] fp32 -> [p][y][x][c] fp16, both copies,
// 16B stores. Block: 256 threads handles (p, y, 64 x-values). (R11 version —
// measured ~5us, near the 50MB/L2-cap floor; the 768-block rewrite regressed.)
__global__ void __launch_bounds__(256) tp_transpose_kernel(const float* __restrict__ in) {
    __shared__ __half sm[64 * 34];
    int p  = blockIdx.z;
    int y  = blockIdx.y;
    int xb = blockIdx.x * 64;

    #pragma unroll
    for (int i = threadIdx.x; i < 64 * 32; i += 256) {
        int c = i >> 6, xl = i & 63;
        sm[xl * 34 + c] = __float2half(__ldg(in + (((p * CC + c) * RR + y) * RR) + xb + xl));
    }
    __syncthreads();

    int xl = threadIdx.x >> 2, q = threadIdx.x & 3;
    const unsigned* s = reinterpret_cast<const unsigned*>(sm + xl * 34 + q * 8);
    uint4 v = make_uint4(s[0], s[1], s[2], s[3]);
    size_t pos4 = ((size_t)((p * RR + y) * RR) + xb + xl) * 4 + q;
    uint4* g = reinterpret_cast<uint4*>(g_tph);
    g[pos4] = v;
    if (pos4 >= 4) g[OFF4 + pos4 - 4] = v;
}

__device__ __forceinline__ __half2 u2h2(unsigned u) {
    return *reinterpret_cast<__half2*>(&u);
}
__device__ __forceinline__ unsigned h22u(__half2 h) {
    return *reinterpret_cast<unsigned*>(&h);
}

// streaming (evict-first) 16B store: keep the 256MB output out of L2's way
__device__ __forceinline__ void stg_cs(float4* p, float4 v) {
    asm volatile("st.global.cs.v4.f32 [%0], {%1, %2, %3, %4};"
                 :: "l"(p), "f"(v.x), "f"(v.y), "f"(v.z), "f"(v.w) : "memory");
}

// streaming (evict-first) scalar load: the 24MB xyz stream is read once —
// don't let it churn L2 against the resident triplane working set.
__device__ __forceinline__ float ldg_cs(const float* p) {
    float v;
    asm volatile("ld.global.cs.f32 %0, [%1];" : "=f"(v) : "l"(p));
    return v;
}

// Warp owns 32 consecutive points. Phase 1: coalesced xyz + SHFL
// redistribution, per-lane axis prep. Phase 2: partial depth-1 pipeline —
// planes 0,1 of iteration it+1 staged ahead (16 buffer regs); plane 2's two
// loads issued at the top of their own iteration. (Best measured config:
// regs 72, occ ~40%, sampler at its L1tex wavefront floor.)
__global__ void __launch_bounds__(128, 7) triplane_sample_kernel(
    const float* __restrict__ xyz, float* __restrict__ out, int M) {
    int lane = threadIdx.x & 31;
    int wgl  = (int)((blockIdx.x * (unsigned)blockDim.x + threadIdx.x) >> 5);
    int m0   = wgl * 32;
    if (m0 >= M) return;

    // ---- phase 1: coalesced xyz (streaming) + shfl redistribution ----
    const float* xb = xyz + (size_t)m0 * 3;
    float r0 = ldg_cs(xb + lane);
    float r1 = ldg_cs(xb + 32 + lane);
    float r2 = ldg_cs(xb + 64 + lane);

    unsigned idx_pack = 0;
    unsigned wpack[3];
    #pragma unroll
    for (int d = 0; d < 3; d++) {
        int f     = 3 * lane + d;
        int chunk = f >> 5, src = f & 31;
        float v0 = __shfl_sync(0xffffffffu, r0, src);
        float v1 = __shfl_sync(0xffffffffu, r1, src);
        float v2 = __shfl_sync(0xffffffffu, r2, src);
        float cv = (chunk == 0) ? v0 : ((chunk == 1) ? v1 : v2);

        float i  = fminf(fmaxf(fmaf(cv, 127.5f, 127.5f), 0.0f), 255.0f);
        int   i0 = (int)i;                 // trunc == floor (i >= 0)
        float f1 = i - (float)i0;          // ==0 exactly at clamped edge
        idx_pack |= ((unsigned)i0) << (8 * d);
        wpack[d]  = h22u(__floats2half2_rn(1.0f - f1, f1));
    }

    int sub   = lane & 7;       // uint4 slot in the 128B x-pair region
    int grp   = lane >> 3;
    int xsel  = sub >> 2;       // 0: x0 tap, 1: x0+1 tap
    int shift = xsel << 4;
    const uint4* tp = reinterpret_cast<const uint4*>(g_tph);

    // stage iteration 'it': metadata SHFLs, all three base addresses,
    // and issue the plane-0/1 loads (plane 2 is issued at consume time)
    auto stage = [&](int it, unsigned& swx, unsigned& swy, unsigned& swz,
                     int& sb2, uint4* t) {
        int src = (it << 2) | grp;
        unsigned idx = __shfl_sync(0xffffffffu, idx_pack, src);
        swx = __shfl_sync(0xffffffffu, wpack[0], src);
        swy = __shfl_sync(0xffffffffu, wpack[1], src);
        swz = __shfl_sync(0xffffffffu, wpack[2], src);

        int ix = idx & 255;
        int iy = (idx >> 8) & 255;
        int iz = (idx >> 16) & 255;
        int cy = ((iy & 1) ? OFF4 : 0) + ((iy & 0xFE) << 2) + sub;
        int cz = ((iz & 1) ? OFF4 : 0) + ((iz & 0xFE) << 2) + sub;
        int b0 = cy + 0 * (RR * RR * 4) + (ix << 10);
        int b1 = cz + 1 * (RR * RR * 4) + (ix << 10);
        sb2    = cy + 2 * (RR * RR * 4) + (iz << 10);

        t[0] = __ldg(tp + b0);
        t[1] = __ldg(tp + b0 + 1024);   // row ix+1 (pad-safe)
        t[2] = __ldg(tp + b1);
        t[3] = __ldg(tp + b1 + 1024);
    };

    // ---- phase 2: 8 iterations x 4 points ----
    unsigned cwx, cwy, cwz;
    int cb2;
    uint4 cur[4];
    stage(0, cwx, cwy, cwz, cb2, cur);

    #pragma unroll
    for (int it = 0; it < 8; it++) {
        // plane 2 loads for the CURRENT iteration — issued first, consumed last
        uint4 t20u = __ldg(tp + cb2);
        uint4 t21u = __ldg(tp + cb2 + 1024);

        // stage next iteration (planes 0,1 + metadata) while t2* are in flight
        unsigned nwx, nwy, nwz;
        int nb2;
        uint4 nxt[4];
        if (it < 7) stage(it + 1, nwx, nwy, nwz, nb2, nxt);

        // weight splats
        auto mkw = [&](unsigned cwt, unsigned rwt, __half2& w0, __half2& w1) {
            __half2 wxh = u2h2(__byte_perm(cwt >> shift, 0, 0x1010));
            unsigned whu = h22u(__hmul2(u2h2(rwt), wxh));
            w0 = u2h2(__byte_perm(whu, 0, 0x1010));
            w1 = u2h2(__byte_perm(whu, 0, 0x3232));
        };
        __half2 w00, w01, w10, w11, w20, w21;
        mkw(cwy, cwx, w00, w01);   // plane0: col=y row=x
        mkw(cwz, cwx, w10, w11);   // plane1: col=z row=x
        mkw(cwy, cwz, w20, w21);   // plane2: col=y row=z

        const __half2* v00 = reinterpret_cast<const __half2*>(&cur[0]);
        const __half2* v01 = reinterpret_cast<const __half2*>(&cur[1]);
        const __half2* v10 = reinterpret_cast<const __half2*>(&cur[2]);
        const __half2* v11 = reinterpret_cast<const __half2*>(&cur[3]);
        const __half2* v20 = reinterpret_cast<const __half2*>(&t20u);
        const __half2* v21 = reinterpret_cast<const __half2*>(&t21u);

        __half2 acc[4];
        // planes 0,1 first (staged an iteration ago), plane 2 last
        #pragma unroll
        for (int j = 0; j < 4; j++) {
            __half2 a = __hmul2(v00[j], w00);
            a = __hfma2(v01[j], w01, a);
            a = __hfma2(v10[j], w10, a);
            acc[j] = __hfma2(v11[j], w11, a);
        }
        #pragma unroll
        for (int j = 0; j < 4; j++) {
            acc[j] = __hfma2(v20[j], w20, acc[j]);
            acc[j] = __hfma2(v21[j], w21, acc[j]);
        }

        // butterfly-sum the two x halves (partner = lane ^ 4)
        #pragma unroll
        for (int j = 0; j < 4; j++) {
            unsigned u = __shfl_xor_sync(0xffffffffu, h22u(acc[j]), 4);
            acc[j] = __hadd2(acc[j], u2h2(u));
        }

        int m  = m0 + (it << 2) + grp;
        int jb = xsel * 2;
        float2 f0 = __half22float2(acc[jb]);
        float2 f1 = __half22float2(acc[jb + 1]);
        stg_cs(reinterpret_cast<float4*>(out) + (size_t)m * 8 + (sub & 3) * 2 + xsel,
               make_float4(f0.x, f0.y, f1.x, f1.y));

        if (it < 7) {
            #pragma unroll
            for (int k = 0; k < 4; k++) cur[k] = nxt[k];
            cwx = nwx; cwy = nwy; cwz = nwz; cb2 = nb2;
        }
    }
}

extern "C" void kernel_launch(void* const* d_in, const int* in_sizes, int n_in,
                              void* d_out, int out_size) {
    const float* xyz      = (const float*)d_in[0];  // (M,3) float32
    const float* triplane = (const float*)d_in[1];  // (3,32,256,256) float32
    float* out = (float*)d_out;                      // (M,32) float32
    int M = in_sizes[0] / 3;

    {
        dim3 block(256, 1, 1);
        dim3 grid(RR / 64, RR, 3);
        tp_transpose_kernel<<<grid, block>>>(triplane);
    }
    {
        int threads = 128;                  // 4 warps = 128 points per block
        int warps   = (M + 31) / 32;
        int blocks  = (warps * 32 + threads - 1) / threads;
        triplane_sample_kernel<<<blocks, threads>>>(xyz, out, M);
    }
}